// round 1
// baseline (speedup 1.0000x reference)
#include <cuda_runtime.h>
#include <cstdint>

#define HIDDEN   1024
#define NLAYERS  20
#define M_TOTAL  8192

#define BM 128
#define BN 128
#define BK 32
#define LDT 36                 // BK + 4 padding (floats) -> conflict-free frag loads
#define STAGES 3
#define TILE_F (BM*LDT)        // 4608 floats per operand per stage
#define SMEM_BYTES (STAGES*2*TILE_F*4)   // 110592

// Scratch for the pre-summed, pre-scaled, tf32-rounded weight matrix [N=1024][K=1024]
__device__ float g_wsum[HIDDEN*HIDDEN];

// ---------------------------------------------------------------------------
// Kernel 0: W = (1/20) * sum_l conv_w[l], rounded to tf32 (round-to-nearest)
// ---------------------------------------------------------------------------
__device__ __forceinline__ float round_tf32(float f) {
    unsigned u;
    asm("cvt.rna.tf32.f32 %0, %1;" : "=r"(u) : "f"(f));
    return __uint_as_float(u);
}

__global__ void wsum_kernel(const float* __restrict__ cw) {
    int i4 = blockIdx.x * blockDim.x + threadIdx.x;   // 0 .. 262143 (float4 index)
    const float4* cw4 = (const float4*)cw;
    float4 acc = cw4[i4];
#pragma unroll
    for (int l = 1; l < NLAYERS; ++l) {
        float4 v = cw4[l * (HIDDEN*HIDDEN/4) + i4];
        acc.x += v.x; acc.y += v.y; acc.z += v.z; acc.w += v.w;
    }
    const float s = 1.0f / (float)NLAYERS;
    float4 r;
    r.x = round_tf32(acc.x * s);
    r.y = round_tf32(acc.y * s);
    r.z = round_tf32(acc.z * s);
    r.w = round_tf32(acc.w * s);
    ((float4*)g_wsum)[i4] = r;
}

// ---------------------------------------------------------------------------
// Kernel 1: out[m][n] = sum_k A[m][k] * W[n][k]    (tf32 tensor-core GEMM)
// A: [8192,1024] row-major (K contiguous), W: [1024,1024] (K contiguous)
// -> mma.sync m16n8k8 row.col, both operands K-major.
// ---------------------------------------------------------------------------
__device__ __forceinline__ unsigned cvt_tf32(float f) {
    unsigned u;
    asm("cvt.rna.tf32.f32 %0, %1;" : "=r"(u) : "f"(f));
    return u;
}
__device__ __forceinline__ void cp16(unsigned saddr, const void* gptr) {
    asm volatile("cp.async.cg.shared.global [%0], [%1], 16;" :: "r"(saddr), "l"(gptr));
}

__global__ void __launch_bounds__(256, 1)
gemm_kernel(const float* __restrict__ A, float* __restrict__ out) {
    extern __shared__ float smem[];
    float* sA = smem;
    float* sB = smem + STAGES * TILE_F;

    const int tid  = threadIdx.x;
    const int lane = tid & 31;
    const int warp = tid >> 5;
    const int wm   = (warp & 1) * 64;    // warp M offset within CTA tile
    const int wn   = (warp >> 1) * 32;   // warp N offset within CTA tile
    const int mrow = lane >> 2;          // 0..7
    const int kcol = lane & 3;           // 0..3

    const float* Ag = A       + (size_t)(blockIdx.y * BM) * HIDDEN;
    const float* Bg = g_wsum  + (size_t)(blockIdx.x * BN) * HIDDEN;

    const int lr = tid >> 3;          // 0..31  (row within 32-row chunk)
    const int lc = (tid & 7) * 4;     // 0,4,...,28 (float col)

    const unsigned sAu = (unsigned)__cvta_generic_to_shared(sA);
    const unsigned sBu = (unsigned)__cvta_generic_to_shared(sB);

    float acc[4][4][4];
#pragma unroll
    for (int mi = 0; mi < 4; ++mi)
#pragma unroll
        for (int ni = 0; ni < 4; ++ni)
#pragma unroll
            for (int c = 0; c < 4; ++c) acc[mi][ni][c] = 0.0f;

    // --- async stage loader ---
    auto load_stage = [&](int stage, int k0) {
        unsigned ab = sAu + (unsigned)(stage * TILE_F) * 4u;
        unsigned bb = sBu + (unsigned)(stage * TILE_F) * 4u;
#pragma unroll
        for (int i = 0; i < 4; ++i) {
            int r = i * 32 + lr;
            cp16(ab + (unsigned)(r * LDT + lc) * 4u, Ag + (size_t)r * HIDDEN + k0 + lc);
            cp16(bb + (unsigned)(r * LDT + lc) * 4u, Bg + (size_t)r * HIDDEN + k0 + lc);
        }
        asm volatile("cp.async.commit_group;");
    };

    load_stage(0, 0);
    load_stage(1, BK);

    const int KT = HIDDEN / BK;   // 32
    for (int kt = 0; kt < KT; ++kt) {
        asm volatile("cp.async.wait_group 1;");
        __syncthreads();
        if (kt + 2 < KT) load_stage((kt + 2) % STAGES, (kt + 2) * BK);

        const float* a = sA + (kt % STAGES) * TILE_F;
        const float* b = sB + (kt % STAGES) * TILE_F;

#pragma unroll
        for (int kk = 0; kk < 4; ++kk) {            // 4 x (k=8) steps
            unsigned af[4][4];
            unsigned bf[4][2];
#pragma unroll
            for (int mi = 0; mi < 4; ++mi) {
                const float* ap = a + (wm + mi * 16 + mrow) * LDT + kk * 8 + kcol;
                af[mi][0] = cvt_tf32(ap[0]);
                af[mi][1] = cvt_tf32(ap[8 * LDT]);
                af[mi][2] = cvt_tf32(ap[4]);
                af[mi][3] = cvt_tf32(ap[8 * LDT + 4]);
            }
#pragma unroll
            for (int ni = 0; ni < 4; ++ni) {
                const float* bp = b + (wn + ni * 8 + mrow) * LDT + kk * 8 + kcol;
                bf[ni][0] = __float_as_uint(bp[0]);   // W pre-rounded to tf32
                bf[ni][1] = __float_as_uint(bp[4]);
            }
#pragma unroll
            for (int mi = 0; mi < 4; ++mi)
#pragma unroll
                for (int ni = 0; ni < 4; ++ni)
                    asm volatile(
                        "mma.sync.aligned.m16n8k8.row.col.f32.tf32.tf32.f32 "
                        "{%0,%1,%2,%3}, {%4,%5,%6,%7}, {%8,%9}, {%0,%1,%2,%3};"
                        : "+f"(acc[mi][ni][0]), "+f"(acc[mi][ni][1]),
                          "+f"(acc[mi][ni][2]), "+f"(acc[mi][ni][3])
                        : "r"(af[mi][0]), "r"(af[mi][1]), "r"(af[mi][2]), "r"(af[mi][3]),
                          "r"(bf[ni][0]), "r"(bf[ni][1]));
        }
    }

    // --- epilogue: raw GEMM result to d_out (RMS-norm is a second pass) ---
    const int gm0 = blockIdx.y * BM + wm + mrow;
    const int gn0 = blockIdx.x * BN + wn + 2 * kcol;
#pragma unroll
    for (int mi = 0; mi < 4; ++mi) {
#pragma unroll
        for (int ni = 0; ni < 4; ++ni) {
            int gm = gm0 + mi * 16;
            int gn = gn0 + ni * 8;
            *(float2*)(out + (size_t)gm * HIDDEN + gn)       = make_float2(acc[mi][ni][0], acc[mi][ni][1]);
            *(float2*)(out + (size_t)(gm + 8) * HIDDEN + gn) = make_float2(acc[mi][ni][2], acc[mi][ni][3]);
        }
    }
}

// ---------------------------------------------------------------------------
// Kernel 2: in-place RMS-norm per row:  x * sqrt(H) / sqrt(sum x^2 + EPS*H) * w
// ---------------------------------------------------------------------------
__global__ void __launch_bounds__(256)
rmsnorm_kernel(float* __restrict__ out, const float* __restrict__ nw) {
    const int row = blockIdx.x;
    float4* p = (float4*)(out + (size_t)row * HIDDEN);
    float4 v = p[threadIdx.x];

    float ss = v.x * v.x + v.y * v.y + v.z * v.z + v.w * v.w;
#pragma unroll
    for (int o = 16; o > 0; o >>= 1) ss += __shfl_xor_sync(0xFFFFFFFFu, ss, o);

    __shared__ float wsum[8];
    __shared__ float s_scale;
    if ((threadIdx.x & 31) == 0) wsum[threadIdx.x >> 5] = ss;
    __syncthreads();
    if (threadIdx.x == 0) {
        float t = 0.0f;
#pragma unroll
        for (int i = 0; i < 8; ++i) t += wsum[i];
        // norm = sqrt(sum + EPS*H);  scale = sqrt(H)/norm
        s_scale = 32.0f * rsqrtf(t + 1.024e-3f);
    }
    __syncthreads();
    const float sc = s_scale;

    float4 w = ((const float4*)nw)[threadIdx.x];
    v.x = v.x * sc * w.x;
    v.y = v.y * sc * w.y;
    v.z = v.z * sc * w.z;
    v.w = v.w * sc * w.w;
    p[threadIdx.x] = v;
}

// ---------------------------------------------------------------------------
extern "C" void kernel_launch(void* const* d_in, const int* in_sizes, int n_in,
                              void* d_out, int out_size) {
    const float* x  = (const float*)d_in[0];   // [2,4096,1024] fp32
    const float* cw = (const float*)d_in[1];   // [20,1024,1024] fp32
    const float* nw = (const float*)d_in[2];   // [1024] fp32
    float* out = (float*)d_out;                // [2,4096,1024] fp32

    (void)in_sizes; (void)n_in; (void)out_size;

    // Stage 0: weight pre-reduction (262144 float4 elements)
    wsum_kernel<<<HIDDEN*HIDDEN/4/256, 256>>>(cw);

    // Stage 1: tf32 GEMM
    cudaFuncSetAttribute(gemm_kernel, cudaFuncAttributeMaxDynamicSharedMemorySize, SMEM_BYTES);
    dim3 grid(HIDDEN / BN, M_TOTAL / BM);   // (8, 64)
    gemm_kernel<<<grid, 256, SMEM_BYTES>>>(x, out);

    // Stage 2: in-place RMS-norm
    rmsnorm_kernel<<<M_TOTAL, 256>>>(out, nw);
}

// round 3
// speedup vs baseline: 1.6468x; 1.6468x over previous
#include <cuda_runtime.h>
#include <cuda_fp16.h>
#include <cstdint>

#define HIDDEN   1024
#define NLAYERS  20
#define M_TOTAL  8192

// ---- GEMM tiling (fp16 HMMA m16n8k16) ----
#define BM 128
#define BN 128
#define BKH 64                    // K per tile, in halves -> 128B smem rows
#define KT (HIDDEN/BKH)           // 16
#define ROWB 128
#define A_STAGE (BM*ROWB)         // 16384 B
#define B_STAGE (BN*ROWB)         // 16384 B
#define STAGE   (A_STAGE+B_STAGE) // 32768 B
#define STAGES  3
#define SMEM_BYTES (STAGES*STAGE) // 98304 B -> 2 CTAs/SM

__device__ __half g_wsum[HIDDEN*HIDDEN];     // 2 MB  (pre-summed weights, fp16)
__device__ __half g_ax[M_TOTAL*HIDDEN];      // 16 MB (activations, fp16)

// ---------------------------------------------------------------------------
__device__ __forceinline__ uint32_t smem_u32(const void* p) {
    uint32_t a;
    asm("{ .reg .u64 t; cvta.to.shared.u64 t, %1; cvt.u32.u64 %0, t; }" : "=r"(a) : "l"(p));
    return a;
}
__device__ __forceinline__ void cp16(uint32_t saddr, const void* g) {
    asm volatile("cp.async.cg.shared.global [%0], [%1], 16;" :: "r"(saddr), "l"(g));
}

// ---------------------------------------------------------------------------
// Kernel 0 (fused prep):
//   blocks [0, 8192):    g_ax  = fp16(x)                 (8M elems)
//   blocks [8192, 9216): g_wsum = fp16(mean_l conv_w[l]) (1M elems)
// ---------------------------------------------------------------------------
__global__ void __launch_bounds__(256)
prep_kernel(const float* __restrict__ x, const float* __restrict__ cw) {
    const int b = blockIdx.x, t = threadIdx.x;
    if (b < M_TOTAL * HIDDEN / 1024) {
        const int i4 = b * 256 + t;                    // float4 index, 0..2M-1
        float4 v = ((const float4*)x)[i4];
        __half2 h0 = __floats2half2_rn(v.x, v.y);
        __half2 h1 = __floats2half2_rn(v.z, v.w);
        ((__half2*)g_ax)[i4 * 2 + 0] = h0;
        ((__half2*)g_ax)[i4 * 2 + 1] = h1;
    } else {
        const int i4 = (b - M_TOTAL * HIDDEN / 1024) * 256 + t;   // 0..262143
        const float4* cw4 = (const float4*)cw;
        float4 a0 = cw4[i4];
        float4 a1 = cw4[(HIDDEN*HIDDEN/4) + i4];
#pragma unroll
        for (int l = 2; l < NLAYERS; l += 2) {
            float4 v0 = cw4[l       * (HIDDEN*HIDDEN/4) + i4];
            float4 v1 = cw4[(l + 1) * (HIDDEN*HIDDEN/4) + i4];
            a0.x += v0.x; a0.y += v0.y; a0.z += v0.z; a0.w += v0.w;
            a1.x += v1.x; a1.y += v1.y; a1.z += v1.z; a1.w += v1.w;
        }
        const float s = 1.0f / (float)NLAYERS;
        __half2 h0 = __floats2half2_rn((a0.x + a1.x) * s, (a0.y + a1.y) * s);
        __half2 h1 = __floats2half2_rn((a0.z + a1.z) * s, (a0.w + a1.w) * s);
        ((__half2*)g_wsum)[i4 * 2 + 0] = h0;
        ((__half2*)g_wsum)[i4 * 2 + 1] = h1;
    }
}

// ---------------------------------------------------------------------------
// Kernel 1: fp16 GEMM  out[m][n] = sum_k Ax[m][k] * Wsum[n][k]
//   CTA 128x128, warp 64x32, mma m16n8k16 row.col, 3-stage cp.async pipeline
// ---------------------------------------------------------------------------
__global__ void __launch_bounds__(256, 2)
gemm_kernel(float* __restrict__ out) {
    extern __shared__ char smem[];
    const uint32_t sbase = smem_u32(smem);

    const int tid  = threadIdx.x;
    const int lane = tid & 31;
    const int warp = tid >> 5;
    const int wm   = (warp & 1) * 64;
    const int wn   = (warp >> 1) * 32;
    const int mBase = blockIdx.y * BM;
    const int nBase = blockIdx.x * BN;

    float acc[4][4][4];
#pragma unroll
    for (int mi = 0; mi < 4; ++mi)
#pragma unroll
        for (int ni = 0; ni < 4; ++ni)
#pragma unroll
            for (int c = 0; c < 4; ++c) acc[mi][ni][c] = 0.0f;

    auto load_stage = [&](int s, int k0h) {
        const uint32_t sa = sbase + (uint32_t)s * STAGE;
        const uint32_t sb = sa + A_STAGE;
#pragma unroll
        for (int i = 0; i < 4; ++i) {
            const int c = i * 256 + tid;          // 0..1023
            const int row = c >> 3, ch = c & 7;
            const uint32_t off = (uint32_t)c * 16u;
            cp16(sa + (off ^ ((off >> 3) & 0x70u)),
                 g_ax + (size_t)(mBase + row) * HIDDEN + k0h + ch * 8);
        }
#pragma unroll
        for (int i = 0; i < 4; ++i) {
            const int c = i * 256 + tid;
            const int row = c >> 3, ch = c & 7;
            const uint32_t off = (uint32_t)c * 16u;
            cp16(sb + (off ^ ((off >> 3) & 0x70u)),
                 g_wsum + (size_t)(nBase + row) * HIDDEN + k0h + ch * 8);
        }
        asm volatile("cp.async.commit_group;");
    };

    load_stage(0, 0);
    load_stage(1, BKH);

    for (int kt = 0; kt < KT; ++kt) {
        asm volatile("cp.async.wait_group 1;");
        __syncthreads();
        if (kt + 2 < KT) load_stage((kt + 2) % STAGES, (kt + 2) * BKH);
        else             asm volatile("cp.async.commit_group;");   // keep group count in step

        const uint32_t sa = sbase + (uint32_t)(kt % STAGES) * STAGE;
        const uint32_t sb = sa + A_STAGE;

#pragma unroll
        for (int kk = 0; kk < 4; ++kk) {
            const uint32_t colb = (uint32_t)(kk * 32 + (lane >> 4) * 16);
            uint32_t af[4][4], bf[2][4];
#pragma unroll
            for (int mi = 0; mi < 4; ++mi) {
                const uint32_t off = (uint32_t)(wm + mi * 16 + (lane & 15)) * ROWB + colb;
                const uint32_t addr = sa + (off ^ ((off >> 3) & 0x70u));
                asm volatile("ldmatrix.sync.aligned.m8n8.x4.shared.b16 {%0,%1,%2,%3}, [%4];"
                             : "=r"(af[mi][0]), "=r"(af[mi][1]), "=r"(af[mi][2]), "=r"(af[mi][3])
                             : "r"(addr));
            }
#pragma unroll
            for (int np = 0; np < 2; ++np) {
                const uint32_t off = (uint32_t)(wn + np * 16 + (lane & 15)) * ROWB + colb;
                const uint32_t addr = sb + (off ^ ((off >> 3) & 0x70u));
                asm volatile("ldmatrix.sync.aligned.m8n8.x4.shared.b16 {%0,%1,%2,%3}, [%4];"
                             : "=r"(bf[np][0]), "=r"(bf[np][1]), "=r"(bf[np][2]), "=r"(bf[np][3])
                             : "r"(addr));
            }
#pragma unroll
            for (int mi = 0; mi < 4; ++mi) {
#pragma unroll
                for (int np = 0; np < 2; ++np) {
                    asm volatile(
                        "mma.sync.aligned.m16n8k16.row.col.f32.f16.f16.f32 "
                        "{%0,%1,%2,%3}, {%4,%5,%6,%7}, {%8,%9}, {%0,%1,%2,%3};"
                        : "+f"(acc[mi][np*2][0]), "+f"(acc[mi][np*2][1]),
                          "+f"(acc[mi][np*2][2]), "+f"(acc[mi][np*2][3])
                        : "r"(af[mi][0]), "r"(af[mi][1]), "r"(af[mi][2]), "r"(af[mi][3]),
                          "r"(bf[np][0]), "r"(bf[np][2]));
                    asm volatile(
                        "mma.sync.aligned.m16n8k16.row.col.f32.f16.f16.f32 "
                        "{%0,%1,%2,%3}, {%4,%5,%6,%7}, {%8,%9}, {%0,%1,%2,%3};"
                        : "+f"(acc[mi][np*2+1][0]), "+f"(acc[mi][np*2+1][1]),
                          "+f"(acc[mi][np*2+1][2]), "+f"(acc[mi][np*2+1][3])
                        : "r"(af[mi][0]), "r"(af[mi][1]), "r"(af[mi][2]), "r"(af[mi][3]),
                          "r"(bf[np][1]), "r"(bf[np][3]));
                }
            }
        }
    }

    // epilogue
    const int r0 = mBase + wm + (lane >> 2);
    const int c0 = nBase + wn + (lane & 3) * 2;
#pragma unroll
    for (int mi = 0; mi < 4; ++mi) {
#pragma unroll
        for (int ni = 0; ni < 4; ++ni) {
            const int r = r0 + mi * 16;
            const int c = c0 + ni * 8;
            *(float2*)(out + (size_t)r * HIDDEN + c)       = make_float2(acc[mi][ni][0], acc[mi][ni][1]);
            *(float2*)(out + (size_t)(r + 8) * HIDDEN + c) = make_float2(acc[mi][ni][2], acc[mi][ni][3]);
        }
    }
}

// ---------------------------------------------------------------------------
// Kernel 2: in-place RMS-norm:  x * sqrt(H) / sqrt(sum x^2 + EPS*H) * w
// ---------------------------------------------------------------------------
__global__ void __launch_bounds__(256)
rmsnorm_kernel(float* __restrict__ out, const float* __restrict__ nw) {
    const int row = blockIdx.x;
    float4* p = (float4*)(out + (size_t)row * HIDDEN);
    float4 v = p[threadIdx.x];

    float ss = v.x * v.x + v.y * v.y + v.z * v.z + v.w * v.w;
#pragma unroll
    for (int o = 16; o > 0; o >>= 1) ss += __shfl_xor_sync(0xFFFFFFFFu, ss, o);

    __shared__ float wsum[8];
    __shared__ float s_scale;
    if ((threadIdx.x & 31) == 0) wsum[threadIdx.x >> 5] = ss;
    __syncthreads();
    if (threadIdx.x == 0) {
        float t = 0.0f;
#pragma unroll
        for (int i = 0; i < 8; ++i) t += wsum[i];
        s_scale = 32.0f * rsqrtf(t + 1.024e-3f);
    }
    __syncthreads();
    const float sc = s_scale;

    float4 w = ((const float4*)nw)[threadIdx.x];
    v.x = v.x * sc * w.x;
    v.y = v.y * sc * w.y;
    v.z = v.z * sc * w.z;
    v.w = v.w * sc * w.w;
    p[threadIdx.x] = v;
}

// ---------------------------------------------------------------------------
extern "C" void kernel_launch(void* const* d_in, const int* in_sizes, int n_in,
                              void* d_out, int out_size) {
    const float* x  = (const float*)d_in[0];   // [2,4096,1024] fp32
    const float* cw = (const float*)d_in[1];   // [20,1024,1024] fp32
    const float* nw = (const float*)d_in[2];   // [1024] fp32
    float* out = (float*)d_out;                // [2,4096,1024] fp32
    (void)in_sizes; (void)n_in; (void)out_size;

    prep_kernel<<<M_TOTAL*HIDDEN/1024 + HIDDEN*HIDDEN/1024, 256>>>(x, cw);   // 9216 blocks

    cudaFuncSetAttribute(gemm_kernel, cudaFuncAttributeMaxDynamicSharedMemorySize, SMEM_BYTES);
    dim3 grid(HIDDEN / BN, M_TOTAL / BM);   // (8, 64) = 512 CTAs
    gemm_kernel<<<grid, 256, SMEM_BYTES>>>(out);

    rmsnorm_kernel<<<M_TOTAL, 256>>>(out, nw);
}